// round 4
// baseline (speedup 1.0000x reference)
#include <cuda_runtime.h>
#include <math.h>

#define B_   2
#define S_   2048
#define D_   1024
#define H_   16
#define HD_  64
#define R_   257
#define WIN_ 128
#define TOK  (B_*S_)    // 4096
#define C3   (3*D_)     // 3072
#define SMP  68         // smem row pad (floats)

// Scratch (allocation-free rule: __device__ globals)
__device__ float g_qkv[(size_t)TOK * C3];                 // [token][3072], per-head layout h*192 + {q:0..63, k:64..127, v:128..191}
__device__ float g_rp[(size_t)B_ * H_ * S_ * R_];         // [b,h,i,r]

// ---------------------------------------------------------------------------
// Kernel 1: qkv[t, n] = sum_k x[t,k] * Wqkv[n,k] + bqkv[n]
// M=4096, N=3072, K=1024. 128x128x8 tiles, 8x8 per thread, 256 threads.
// ---------------------------------------------------------------------------
__global__ __launch_bounds__(256) void qkv_gemm_kernel(
    const float* __restrict__ x, const float* __restrict__ W,
    const float* __restrict__ bias)
{
    __shared__ float As[8][128];
    __shared__ float Bs[8][128];
    const int tid = threadIdx.x;
    const int m0 = blockIdx.y * 128;
    const int n0 = blockIdx.x * 128;
    const int tr = tid >> 4;       // 0..15
    const int tc = tid & 15;       // 0..15
    const int lr = tid >> 1;       // 0..127 (load row)
    const int lk = (tid & 1) << 2; // 0 or 4 (load k quad)

    const float* xp = x + (size_t)(m0 + lr) * D_ + lk;
    const float* wp = W + (size_t)(n0 + lr) * D_ + lk;

    float acc[8][8];
#pragma unroll
    for (int i = 0; i < 8; i++)
#pragma unroll
        for (int j = 0; j < 8; j++) acc[i][j] = 0.0f;

    for (int k0 = 0; k0 < D_; k0 += 8) {
        float4 av = *(const float4*)(xp + k0);
        float4 bv = *(const float4*)(wp + k0);
        As[lk + 0][lr] = av.x; As[lk + 1][lr] = av.y;
        As[lk + 2][lr] = av.z; As[lk + 3][lr] = av.w;
        Bs[lk + 0][lr] = bv.x; Bs[lk + 1][lr] = bv.y;
        Bs[lk + 2][lr] = bv.z; Bs[lk + 3][lr] = bv.w;
        __syncthreads();
#pragma unroll
        for (int k = 0; k < 8; k++) {
            float a[8], b[8];
#pragma unroll
            for (int i = 0; i < 8; i++) a[i] = As[k][tr * 8 + i];
#pragma unroll
            for (int j = 0; j < 8; j++) b[j] = Bs[k][tc * 8 + j];
#pragma unroll
            for (int i = 0; i < 8; i++)
#pragma unroll
                for (int j = 0; j < 8; j++) acc[i][j] += a[i] * b[j];
        }
        __syncthreads();
    }

#pragma unroll
    for (int i = 0; i < 8; i++) {
        const int m = m0 + tr * 8 + i;
        float* op = g_qkv + (size_t)m * C3 + n0 + tc * 8;
#pragma unroll
        for (int j = 0; j < 8; j += 4) {
            float4 o;
            o.x = acc[i][j + 0] + bias[n0 + tc * 8 + j + 0];
            o.y = acc[i][j + 1] + bias[n0 + tc * 8 + j + 1];
            o.z = acc[i][j + 2] + bias[n0 + tc * 8 + j + 2];
            o.w = acc[i][j + 3] + bias[n0 + tc * 8 + j + 3];
            *(float4*)(op + j) = o;
        }
    }
}

// ---------------------------------------------------------------------------
// Kernel 2: rp[b,h,i,r] = sum_k q[b,h,i,k] * Wr[r,k] + br[r]   (unscaled q)
// Block = 64 queries of one (b,h). 5 chunks of <=64 r-columns. 4x4 per thread.
// ---------------------------------------------------------------------------
__global__ __launch_bounds__(256) void rp_gemm_kernel(
    const float* __restrict__ Wr, const float* __restrict__ br)
{
    __shared__ float Qs[64 * SMP];  // [k][i]
    __shared__ float Ws[64 * SMP];  // [k][r_local]
    const int tid = threadIdx.x;
    const int i0 = blockIdx.x * 64;
    const int h  = blockIdx.y;
    const int b  = blockIdx.z;
    const int tr = tid >> 4, tc = tid & 15;
    const int hb = h * 192;

    // Load Q tile transposed: Qs[k][i] = qkv[(b*S+i0+i)*3072 + h*192 + k]
#pragma unroll
    for (int t = 0; t < 4; t++) {
        int idx = tid + t * 256;
        int row = idx >> 4;
        int k4  = (idx & 15) << 2;
        float4 v = *(const float4*)(g_qkv + (size_t)(b * S_ + i0 + row) * C3 + hb + k4);
        Qs[(k4 + 0) * SMP + row] = v.x;
        Qs[(k4 + 1) * SMP + row] = v.y;
        Qs[(k4 + 2) * SMP + row] = v.z;
        Qs[(k4 + 3) * SMP + row] = v.w;
    }

    float* rpb = g_rp + ((size_t)(b * H_ + h) * S_ + i0) * R_;

    for (int r0 = 0; r0 < R_; r0 += 64) {
        __syncthreads();  // covers Qs load on first iter; Ws reuse on later iters
        // Load Wr chunk transposed: Ws[k][rl] = Wr[r0+rl][k]
#pragma unroll
        for (int t = 0; t < 4; t++) {
            int idx = tid + t * 256;
            int rl  = idx >> 4;
            int k4  = (idx & 15) << 2;
            float4 v = make_float4(0.f, 0.f, 0.f, 0.f);
            if (r0 + rl < R_) v = *(const float4*)(Wr + (size_t)(r0 + rl) * HD_ + k4);
            Ws[(k4 + 0) * SMP + rl] = v.x;
            Ws[(k4 + 1) * SMP + rl] = v.y;
            Ws[(k4 + 2) * SMP + rl] = v.z;
            Ws[(k4 + 3) * SMP + rl] = v.w;
        }
        __syncthreads();

        float acc[4][4];
#pragma unroll
        for (int i = 0; i < 4; i++)
#pragma unroll
            for (int j = 0; j < 4; j++) acc[i][j] = 0.0f;

#pragma unroll 8
        for (int k = 0; k < 64; k++) {
            float4 qa = *(const float4*)(Qs + k * SMP + tr * 4);
            float4 wb = *(const float4*)(Ws + k * SMP + tc * 4);
            float a[4] = {qa.x, qa.y, qa.z, qa.w};
            float w[4] = {wb.x, wb.y, wb.z, wb.w};
#pragma unroll
            for (int i = 0; i < 4; i++)
#pragma unroll
                for (int j = 0; j < 4; j++) acc[i][j] += a[i] * w[j];
        }

#pragma unroll
        for (int i = 0; i < 4; i++) {
            int irow = tr * 4 + i;
#pragma unroll
            for (int j = 0; j < 4; j++) {
                int r = r0 + tc * 4 + j;
                if (r < R_) rpb[(size_t)irow * R_ + r] = acc[i][j] + br[r];
            }
        }
    }
}

// ---------------------------------------------------------------------------
// Kernel 3: flash-style attention with relative-position bias.
// Block = 64 queries of one (b,h); loop over 32 key tiles of 64.
// S[i,j] = (q/8)·k + rp[i, clip(j-i,-128,128)+128]; online softmax; O += P·V.
// ---------------------------------------------------------------------------
__global__ __launch_bounds__(256) void attn_kernel(float* __restrict__ out)
{
    extern __shared__ float sm[];
    float* Qs = sm;                 // [k][i] 64xSMP (pre-scaled by 1/8)
    float* Ks = sm + 64 * SMP;      // [k][j]
    float* Vs = sm + 2 * 64 * SMP;  // [j][d]
    float* Ps = sm + 3 * 64 * SMP;  // [j][i]

    const int tid = threadIdx.x;
    const int q0 = blockIdx.x * 64;
    const int h  = blockIdx.y;
    const int b  = blockIdx.z;
    const int tr = tid >> 4, tc = tid & 15;
    const int hb = h * 192;

    // Load Q tile transposed + pre-scaled (scale = sqrt(d/h) = 8)
#pragma unroll
    for (int t = 0; t < 4; t++) {
        int idx = tid + t * 256;
        int row = idx >> 4;
        int k4  = (idx & 15) << 2;
        float4 v = *(const float4*)(g_qkv + (size_t)(b * S_ + q0 + row) * C3 + hb + k4);
        Qs[(k4 + 0) * SMP + row] = v.x * 0.125f;
        Qs[(k4 + 1) * SMP + row] = v.y * 0.125f;
        Qs[(k4 + 2) * SMP + row] = v.z * 0.125f;
        Qs[(k4 + 3) * SMP + row] = v.w * 0.125f;
    }

    float m[4], l[4], O[4][4];
#pragma unroll
    for (int r = 0; r < 4; r++) {
        m[r] = -1e30f; l[r] = 0.0f;
#pragma unroll
        for (int c = 0; c < 4; c++) O[r][c] = 0.0f;
    }

    const float* rpb = g_rp + ((size_t)(b * H_ + h) * S_ + q0) * R_;

    for (int kt = 0; kt < S_ / 64; kt++) {
        // Load K (transposed) and V (natural) tiles
#pragma unroll
        for (int t = 0; t < 4; t++) {
            int idx = tid + t * 256;
            int row = idx >> 4;
            int k4  = (idx & 15) << 2;
            const float* base = g_qkv + (size_t)(b * S_ + kt * 64 + row) * C3 + hb;
            float4 kv = *(const float4*)(base + 64 + k4);
            float4 vv = *(const float4*)(base + 128 + k4);
            Ks[(k4 + 0) * SMP + row] = kv.x;
            Ks[(k4 + 1) * SMP + row] = kv.y;
            Ks[(k4 + 2) * SMP + row] = kv.z;
            Ks[(k4 + 3) * SMP + row] = kv.w;
            *(float4*)(Vs + row * SMP + k4) = vv;   // aligned: SMP%4==0
        }
        __syncthreads();  // (also covers Qs on first tile)

        // S = Qs·Ks
        float sf[4][4];
#pragma unroll
        for (int i = 0; i < 4; i++)
#pragma unroll
            for (int j = 0; j < 4; j++) sf[i][j] = 0.0f;
#pragma unroll 8
        for (int k = 0; k < 64; k++) {
            float4 qa = *(const float4*)(Qs + k * SMP + tr * 4);
            float4 kb = *(const float4*)(Ks + k * SMP + tc * 4);
            float a[4] = {qa.x, qa.y, qa.z, qa.w};
            float kk[4] = {kb.x, kb.y, kb.z, kb.w};
#pragma unroll
            for (int i = 0; i < 4; i++)
#pragma unroll
                for (int j = 0; j < 4; j++) sf[i][j] += a[i] * kk[j];
        }

        // + relative position bias (gather, L1-resident rows)
#pragma unroll
        for (int r = 0; r < 4; r++) {
            const int i_l = tr * 4 + r;
            const int i_g = q0 + i_l;
            const float* rprow = rpb + (size_t)i_l * R_;
#pragma unroll
            for (int c = 0; c < 4; c++) {
                int off = (kt * 64 + tc * 4 + c) - i_g;
                off = off < -WIN_ ? -WIN_ : (off > WIN_ ? WIN_ : off);
                sf[r][c] += __ldg(rprow + off + WIN_);
            }
        }

        // Online softmax (row groups = 16 lanes sharing tr)
#pragma unroll
        for (int r = 0; r < 4; r++) {
            float mx = fmaxf(fmaxf(sf[r][0], sf[r][1]), fmaxf(sf[r][2], sf[r][3]));
#pragma unroll
            for (int o = 8; o >= 1; o >>= 1)
                mx = fmaxf(mx, __shfl_xor_sync(0xffffffffu, mx, o));
            float mn = fmaxf(m[r], mx);
            float al = __expf(m[r] - mn);
            m[r] = mn;
            float s = 0.0f;
#pragma unroll
            for (int c = 0; c < 4; c++) {
                float p = __expf(sf[r][c] - mn);
                Ps[(tc * 4 + c) * SMP + tr * 4 + r] = p;
                s += p;
            }
#pragma unroll
            for (int o = 8; o >= 1; o >>= 1)
                s += __shfl_xor_sync(0xffffffffu, s, o);
            l[r] = l[r] * al + s;
#pragma unroll
            for (int c = 0; c < 4; c++) O[r][c] *= al;
        }
        __syncthreads();  // Ps visible

        // O += P·V
#pragma unroll 8
        for (int j = 0; j < 64; j++) {
            float4 pv = *(const float4*)(Ps + j * SMP + tr * 4);
            float4 vv = *(const float4*)(Vs + j * SMP + tc * 4);
            float p[4] = {pv.x, pv.y, pv.z, pv.w};
            float v[4] = {vv.x, vv.y, vv.z, vv.w};
#pragma unroll
            for (int r = 0; r < 4; r++)
#pragma unroll
                for (int c = 0; c < 4; c++) O[r][c] += p[r] * v[c];
        }
        __syncthreads();  // before next tile overwrites Ks/Vs/Ps
    }

    // Epilogue: normalize and write out[b, i, h*64 + dim]
#pragma unroll
    for (int r = 0; r < 4; r++) {
        float inv = 1.0f / l[r];
        float4 o;
        o.x = O[r][0] * inv; o.y = O[r][1] * inv;
        o.z = O[r][2] * inv; o.w = O[r][3] * inv;
        *(float4*)(out + (size_t)(b * S_ + q0 + tr * 4 + r) * D_ + h * HD_ + tc * 4) = o;
    }
}

// ---------------------------------------------------------------------------
extern "C" void kernel_launch(void* const* d_in, const int* in_sizes, int n_in,
                              void* d_out, int out_size)
{
    const float* x    = (const float*)d_in[0];
    const float* Wqkv = (const float*)d_in[1];
    const float* bqkv = (const float*)d_in[2];
    const float* Wr   = (const float*)d_in[3];
    const float* br   = (const float*)d_in[4];
    float* out = (float*)d_out;

    dim3 g1(C3 / 128, TOK / 128);   // (24, 32)
    qkv_gemm_kernel<<<g1, 256>>>(x, Wqkv, bqkv);

    dim3 g2(S_ / 64, H_, B_);       // (32, 16, 2)
    rp_gemm_kernel<<<g2, 256>>>(Wr, br);

    const int smem = 4 * 64 * SMP * (int)sizeof(float);  // 69,632 B
    cudaFuncSetAttribute(attn_kernel, cudaFuncAttributeMaxDynamicSharedMemorySize, smem);
    dim3 g3(S_ / 64, H_, B_);
    attn_kernel<<<g3, 256, smem>>>(out);
}

// round 10
// speedup vs baseline: 1.3488x; 1.3488x over previous
#include <cuda_runtime.h>
#include <cuda_bf16.h>
#include <math.h>
#include <stdint.h>

#define B_   2
#define S_   2048
#define D_   1024
#define H_   16
#define HD_  64
#define R_   257
#define WIN_ 128
#define TOK  (B_*S_)    // 4096
#define C3   (3*D_)     // 3072
#define SMP  68         // smem row pad (floats) for SIMT kernels

// Scratch (allocation-free rule: __device__ globals)
__device__ float g_qkv[(size_t)TOK * C3];                 // [token][3072]
__device__ float g_rp[(size_t)B_ * H_ * S_ * R_];         // [b,h,i,r]
__device__ __align__(256) __nv_bfloat16 g_xhi[(size_t)TOK * D_];
__device__ __align__(256) __nv_bfloat16 g_xlo[(size_t)TOK * D_];
__device__ __align__(256) __nv_bfloat16 g_whi[(size_t)C3  * D_];
__device__ __align__(256) __nv_bfloat16 g_wlo[(size_t)C3  * D_];

// ---------------------------------------------------------------------------
// PTX helpers: warp-level HMMA path (no tcgen05 — ptxas target lacks 'a' feats)
// ---------------------------------------------------------------------------
__device__ __forceinline__ uint32_t smem_u32(const void* p) {
    uint32_t a;
    asm("{ .reg .u64 t; cvta.to.shared.u64 t, %1; cvt.u32.u64 %0, t; }"
        : "=r"(a) : "l"(p));
    return a;
}
__device__ __forceinline__ void ldsm4(uint32_t* r, uint32_t a) {
    asm volatile("ldmatrix.sync.aligned.m8n8.x4.shared.b16 {%0,%1,%2,%3}, [%4];"
        : "=r"(r[0]), "=r"(r[1]), "=r"(r[2]), "=r"(r[3]) : "r"(a));
}
__device__ __forceinline__ void mma16816(float* d, const uint32_t* a, const uint32_t* b) {
    asm volatile(
        "mma.sync.aligned.m16n8k16.row.col.f32.bf16.bf16.f32 "
        "{%0,%1,%2,%3}, {%4,%5,%6,%7}, {%8,%9}, {%0,%1,%2,%3};"
        : "+f"(d[0]), "+f"(d[1]), "+f"(d[2]), "+f"(d[3])
        : "r"(a[0]), "r"(a[1]), "r"(a[2]), "r"(a[3]), "r"(b[0]), "r"(b[1]));
}

// ---------------------------------------------------------------------------
// Kernel 0: split fp32 -> bf16 hi/lo pair
// ---------------------------------------------------------------------------
__global__ __launch_bounds__(256) void split_bf16_kernel(
    const float4* __restrict__ src, __nv_bfloat162* __restrict__ hi,
    __nv_bfloat162* __restrict__ lo, int n4)
{
    int i = blockIdx.x * 256 + threadIdx.x;
    if (i >= n4) return;
    float4 v = src[i];
    __nv_bfloat16 hx = __float2bfloat16(v.x);
    __nv_bfloat16 hy = __float2bfloat16(v.y);
    __nv_bfloat16 hz = __float2bfloat16(v.z);
    __nv_bfloat16 hw = __float2bfloat16(v.w);
    __nv_bfloat16 lx = __float2bfloat16(v.x - __bfloat162float(hx));
    __nv_bfloat16 ly = __float2bfloat16(v.y - __bfloat162float(hy));
    __nv_bfloat16 lz = __float2bfloat16(v.z - __bfloat162float(hz));
    __nv_bfloat16 lw = __float2bfloat16(v.w - __bfloat162float(hw));
    __nv_bfloat162 h0; h0.x = hx; h0.y = hy;
    __nv_bfloat162 h1; h1.x = hz; h1.y = hw;
    __nv_bfloat162 l0; l0.x = lx; l0.y = ly;
    __nv_bfloat162 l1; l1.x = lz; l1.y = lw;
    hi[i * 2 + 0] = h0; hi[i * 2 + 1] = h1;
    lo[i * 2 + 0] = l0; lo[i * 2 + 1] = l1;
}

// ---------------------------------------------------------------------------
// Kernel 1: QKV GEMM via mma.sync (bf16x3 split, fp32 accum).
// CTA tile 128(M)x128(N), 8 warps in 4x2 grid, warp tile 32x64 (2x8 m16n8k16).
// K=1024 in 16 chunks of 64. smem tiles padded to 144B rows (conflict-free
// for ldmatrix and uint4 STS).
// ---------------------------------------------------------------------------
#define KC     64
#define SROW   144                     // bytes per smem row (64*2 + 16 pad)
#define TILEB  (128 * SROW)            // 18,432 B per tile
#define OFF_AH 0
#define OFF_AL (1 * TILEB)
#define OFF_BH (2 * TILEB)
#define OFF_BL (3 * TILEB)
#define QKV_SMEM (4 * TILEB)           // 73,728 B

__global__ __launch_bounds__(256, 2) void qkv_mma_kernel(const float* __restrict__ bias)
{
    extern __shared__ char smem[];
    const uint32_t sbase = smem_u32(smem);
    const int tid  = threadIdx.x;
    const int wid  = tid >> 5, lane = tid & 31;
    const int wm   = wid & 3;          // warp M index (4)
    const int wn   = wid >> 2;         // warp N index (2)
    const int n0   = blockIdx.x * 128;
    const int m0   = blockIdx.y * 128;

    const __nv_bfloat16* Ah = g_xhi + (size_t)m0 * D_;
    const __nv_bfloat16* Al = g_xlo + (size_t)m0 * D_;
    const __nv_bfloat16* Bh = g_whi + (size_t)n0 * D_;
    const __nv_bfloat16* Bl = g_wlo + (size_t)n0 * D_;

    // per-thread smem ldmatrix base addresses
    const uint32_t a_row  = (uint32_t)(wm * 32 + ((lane >> 3) & 1) * 8 + (lane & 7));
    const uint32_t a_colb = (uint32_t)((lane >> 4) * 16);
    const uint32_t aAH = sbase + OFF_AH + a_row * SROW + a_colb;
    const uint32_t aAL = sbase + OFF_AL + a_row * SROW + a_colb;
    const uint32_t b_row  = (uint32_t)(wn * 64 + ((lane >> 4) << 3) + (lane & 7));
    const uint32_t b_colb = (uint32_t)(((lane >> 3) & 1) * 16);
    const uint32_t bBH = sbase + OFF_BH + b_row * SROW + b_colb;
    const uint32_t bBL = sbase + OFF_BL + b_row * SROW + b_colb;

    float acc[2][8][4];
#pragma unroll
    for (int mt = 0; mt < 2; mt++)
#pragma unroll
        for (int nt = 0; nt < 8; nt++)
#pragma unroll
            for (int e = 0; e < 4; e++) acc[mt][nt][e] = 0.0f;

    // global->smem load indexing: idx -> (row, 16B column)
    const int lrow = tid >> 3;          // base row for t=0 (rows advance by 32)
    const int lc8  = tid & 7;           // 16-byte column (8 per 128B row)

    for (int ch = 0; ch < D_ / KC; ch++) {
        const int k0 = ch * KC;
        __syncthreads();   // previous chunk's compute done before overwrite
#pragma unroll
        for (int t = 0; t < 4; t++) {
            int row = lrow + t * 32;
            uint32_t so = (uint32_t)(row * SROW + lc8 * 16);
            size_t gsrc = (size_t)row * D_ + k0 + lc8 * 8;
            *(uint4*)(smem + OFF_AH + so) = *(const uint4*)(Ah + gsrc);
            *(uint4*)(smem + OFF_AL + so) = *(const uint4*)(Al + gsrc);
            *(uint4*)(smem + OFF_BH + so) = *(const uint4*)(Bh + gsrc);
            *(uint4*)(smem + OFF_BL + so) = *(const uint4*)(Bl + gsrc);
        }
        __syncthreads();

#pragma unroll
        for (int ks = 0; ks < 4; ks++) {
            uint32_t aH[2][4], aL[2][4];
            ldsm4(aH[0], aAH + ks * 32);
            ldsm4(aH[1], aAH + 16 * SROW + ks * 32);
            ldsm4(aL[0], aAL + ks * 32);
            ldsm4(aL[1], aAL + 16 * SROW + ks * 32);
#pragma unroll
            for (int ntp = 0; ntp < 4; ntp++) {
                uint32_t bH[4], bL[4];
                ldsm4(bH, bBH + ntp * (16 * SROW) + ks * 32);
                ldsm4(bL, bBL + ntp * (16 * SROW) + ks * 32);
#pragma unroll
                for (int mt = 0; mt < 2; mt++) {
#pragma unroll
                    for (int ntl = 0; ntl < 2; ntl++) {
                        float* d = acc[mt][ntp * 2 + ntl];
                        mma16816(d, aH[mt], bH + ntl * 2);
                        mma16816(d, aH[mt], bL + ntl * 2);
                        mma16816(d, aL[mt], bH + ntl * 2);
                    }
                }
            }
        }
    }

    // Epilogue: bias add + direct float2 stores
    const int g = lane >> 2, tq = lane & 3;
#pragma unroll
    for (int mt = 0; mt < 2; mt++) {
        const int row0 = m0 + wm * 32 + mt * 16 + g;
#pragma unroll
        for (int nt = 0; nt < 8; nt++) {
            const int col = n0 + wn * 64 + nt * 8 + tq * 2;
            float2 bv = *(const float2*)(bias + col);
            float2 v0, v1;
            v0.x = acc[mt][nt][0] + bv.x; v0.y = acc[mt][nt][1] + bv.y;
            v1.x = acc[mt][nt][2] + bv.x; v1.y = acc[mt][nt][3] + bv.y;
            *(float2*)(g_qkv + (size_t)row0 * C3 + col)       = v0;
            *(float2*)(g_qkv + (size_t)(row0 + 8) * C3 + col) = v1;
        }
    }
}

// ---------------------------------------------------------------------------
// Kernel 2: rp[b,h,i,r] = sum_k q[b,h,i,k] * Wr[r,k] + br[r]   (unscaled q)
// ---------------------------------------------------------------------------
__global__ __launch_bounds__(256) void rp_gemm_kernel(
    const float* __restrict__ Wr, const float* __restrict__ br)
{
    __shared__ float Qs[64 * SMP];  // [k][i]
    __shared__ float Ws[64 * SMP];  // [k][r_local]
    const int tid = threadIdx.x;
    const int i0 = blockIdx.x * 64;
    const int h  = blockIdx.y;
    const int b  = blockIdx.z;
    const int tr = tid >> 4, tc = tid & 15;
    const int hb = h * 192;

#pragma unroll
    for (int t = 0; t < 4; t++) {
        int idx = tid + t * 256;
        int row = idx >> 4;
        int k4  = (idx & 15) << 2;
        float4 v = *(const float4*)(g_qkv + (size_t)(b * S_ + i0 + row) * C3 + hb + k4);
        Qs[(k4 + 0) * SMP + row] = v.x;
        Qs[(k4 + 1) * SMP + row] = v.y;
        Qs[(k4 + 2) * SMP + row] = v.z;
        Qs[(k4 + 3) * SMP + row] = v.w;
    }

    float* rpb = g_rp + ((size_t)(b * H_ + h) * S_ + i0) * R_;

    for (int r0 = 0; r0 < R_; r0 += 64) {
        __syncthreads();
#pragma unroll
        for (int t = 0; t < 4; t++) {
            int idx = tid + t * 256;
            int rl  = idx >> 4;
            int k4  = (idx & 15) << 2;
            float4 v = make_float4(0.f, 0.f, 0.f, 0.f);
            if (r0 + rl < R_) v = *(const float4*)(Wr + (size_t)(r0 + rl) * HD_ + k4);
            Ws[(k4 + 0) * SMP + rl] = v.x;
            Ws[(k4 + 1) * SMP + rl] = v.y;
            Ws[(k4 + 2) * SMP + rl] = v.z;
            Ws[(k4 + 3) * SMP + rl] = v.w;
        }
        __syncthreads();

        float acc[4][4];
#pragma unroll
        for (int i = 0; i < 4; i++)
#pragma unroll
            for (int j = 0; j < 4; j++) acc[i][j] = 0.0f;

#pragma unroll 8
        for (int k = 0; k < 64; k++) {
            float4 qa = *(const float4*)(Qs + k * SMP + tr * 4);
            float4 wb = *(const float4*)(Ws + k * SMP + tc * 4);
            float a[4] = {qa.x, qa.y, qa.z, qa.w};
            float w[4] = {wb.x, wb.y, wb.z, wb.w};
#pragma unroll
            for (int i = 0; i < 4; i++)
#pragma unroll
                for (int j = 0; j < 4; j++) acc[i][j] += a[i] * w[j];
        }

#pragma unroll
        for (int i = 0; i < 4; i++) {
            int irow = tr * 4 + i;
#pragma unroll
            for (int j = 0; j < 4; j++) {
                int r = r0 + tc * 4 + j;
                if (r < R_) rpb[(size_t)irow * R_ + r] = acc[i][j] + br[r];
            }
        }
    }
}

// ---------------------------------------------------------------------------
// Kernel 3: flash-style attention with relative-position bias (SIMT fp32).
// ---------------------------------------------------------------------------
__global__ __launch_bounds__(256) void attn_kernel(float* __restrict__ out)
{
    extern __shared__ float sm[];
    float* Qs = sm;                 // [k][i] 64xSMP (pre-scaled by 1/8)
    float* Ks = sm + 64 * SMP;      // [k][j]
    float* Vs = sm + 2 * 64 * SMP;  // [j][d]
    float* Ps = sm + 3 * 64 * SMP;  // [j][i]

    const int tid = threadIdx.x;
    const int q0 = blockIdx.x * 64;
    const int h  = blockIdx.y;
    const int b  = blockIdx.z;
    const int tr = tid >> 4, tc = tid & 15;
    const int hb = h * 192;

#pragma unroll
    for (int t = 0; t < 4; t++) {
        int idx = tid + t * 256;
        int row = idx >> 4;
        int k4  = (idx & 15) << 2;
        float4 v = *(const float4*)(g_qkv + (size_t)(b * S_ + q0 + row) * C3 + hb + k4);
        Qs[(k4 + 0) * SMP + row] = v.x * 0.125f;
        Qs[(k4 + 1) * SMP + row] = v.y * 0.125f;
        Qs[(k4 + 2) * SMP + row] = v.z * 0.125f;
        Qs[(k4 + 3) * SMP + row] = v.w * 0.125f;
    }

    float m[4], l[4], O[4][4];
#pragma unroll
    for (int r = 0; r < 4; r++) {
        m[r] = -1e30f; l[r] = 0.0f;
#pragma unroll
        for (int c = 0; c < 4; c++) O[r][c] = 0.0f;
    }

    const float* rpb = g_rp + ((size_t)(b * H_ + h) * S_ + q0) * R_;

    for (int kt = 0; kt < S_ / 64; kt++) {
#pragma unroll
        for (int t = 0; t < 4; t++) {
            int idx = tid + t * 256;
            int row = idx >> 4;
            int k4  = (idx & 15) << 2;
            const float* base = g_qkv + (size_t)(b * S_ + kt * 64 + row) * C3 + hb;
            float4 kv = *(const float4*)(base + 64 + k4);
            float4 vv = *(const float4*)(base + 128 + k4);
            Ks[(k4 + 0) * SMP + row] = kv.x;
            Ks[(k4 + 1) * SMP + row] = kv.y;
            Ks[(k4 + 2) * SMP + row] = kv.z;
            Ks[(k4 + 3) * SMP + row] = kv.w;
            *(float4*)(Vs + row * SMP + k4) = vv;
        }
        __syncthreads();

        float sf[4][4];
#pragma unroll
        for (int i = 0; i < 4; i++)
#pragma unroll
            for (int j = 0; j < 4; j++) sf[i][j] = 0.0f;
#pragma unroll 8
        for (int k = 0; k < 64; k++) {
            float4 qa = *(const float4*)(Qs + k * SMP + tr * 4);
            float4 kb = *(const float4*)(Ks + k * SMP + tc * 4);
            float a[4] = {qa.x, qa.y, qa.z, qa.w};
            float kk[4] = {kb.x, kb.y, kb.z, kb.w};
#pragma unroll
            for (int i = 0; i < 4; i++)
#pragma unroll
                for (int j = 0; j < 4; j++) sf[i][j] += a[i] * kk[j];
        }

#pragma unroll
        for (int r = 0; r < 4; r++) {
            const int i_l = tr * 4 + r;
            const int i_g = q0 + i_l;
            const float* rprow = rpb + (size_t)i_l * R_;
#pragma unroll
            for (int c = 0; c < 4; c++) {
                int off = (kt * 64 + tc * 4 + c) - i_g;
                off = off < -WIN_ ? -WIN_ : (off > WIN_ ? WIN_ : off);
                sf[r][c] += __ldg(rprow + off + WIN_);
            }
        }

#pragma unroll
        for (int r = 0; r < 4; r++) {
            float mx = fmaxf(fmaxf(sf[r][0], sf[r][1]), fmaxf(sf[r][2], sf[r][3]));
#pragma unroll
            for (int o = 8; o >= 1; o >>= 1)
                mx = fmaxf(mx, __shfl_xor_sync(0xffffffffu, mx, o));
            float mn = fmaxf(m[r], mx);
            float al = __expf(m[r] - mn);
            m[r] = mn;
            float s = 0.0f;
#pragma unroll
            for (int c = 0; c < 4; c++) {
                float p = __expf(sf[r][c] - mn);
                Ps[(tc * 4 + c) * SMP + tr * 4 + r] = p;
                s += p;
            }
#pragma unroll
            for (int o = 8; o >= 1; o >>= 1)
                s += __shfl_xor_sync(0xffffffffu, s, o);
            l[r] = l[r] * al + s;
#pragma unroll
            for (int c = 0; c < 4; c++) O[r][c] *= al;
        }
        __syncthreads();

#pragma unroll 8
        for (int j = 0; j < 64; j++) {
            float4 pv = *(const float4*)(Ps + j * SMP + tr * 4);
            float4 vv = *(const float4*)(Vs + j * SMP + tc * 4);
            float p[4] = {pv.x, pv.y, pv.z, pv.w};
            float v[4] = {vv.x, vv.y, vv.z, vv.w};
#pragma unroll
            for (int r = 0; r < 4; r++)
#pragma unroll
                for (int c = 0; c < 4; c++) O[r][c] += p[r] * v[c];
        }
        __syncthreads();
    }

#pragma unroll
    for (int r = 0; r < 4; r++) {
        float inv = 1.0f / l[r];
        float4 o;
        o.x = O[r][0] * inv; o.y = O[r][1] * inv;
        o.z = O[r][2] * inv; o.w = O[r][3] * inv;
        *(float4*)(out + (size_t)(b * S_ + q0 + tr * 4 + r) * D_ + h * HD_ + tc * 4) = o;
    }
}

// ---------------------------------------------------------------------------
extern "C" void kernel_launch(void* const* d_in, const int* in_sizes, int n_in,
                              void* d_out, int out_size)
{
    const float* x    = (const float*)d_in[0];
    const float* Wqkv = (const float*)d_in[1];
    const float* bqkv = (const float*)d_in[2];
    const float* Wr   = (const float*)d_in[3];
    const float* br   = (const float*)d_in[4];
    float* out = (float*)d_out;

    __nv_bfloat162 *xhi, *xlo, *whi, *wlo;
    cudaGetSymbolAddress((void**)&xhi, g_xhi);
    cudaGetSymbolAddress((void**)&xlo, g_xlo);
    cudaGetSymbolAddress((void**)&whi, g_whi);
    cudaGetSymbolAddress((void**)&wlo, g_wlo);

    // bf16 hi/lo splits of X and Wqkv
    split_bf16_kernel<<<(TOK * D_ / 4 + 255) / 256, 256>>>(
        (const float4*)x, xhi, xlo, TOK * D_ / 4);
    split_bf16_kernel<<<(C3 * D_ / 4 + 255) / 256, 256>>>(
        (const float4*)Wqkv, whi, wlo, C3 * D_ / 4);

    // QKV GEMM on tensor cores (warp mma.sync)
    cudaFuncSetAttribute(qkv_mma_kernel,
                         cudaFuncAttributeMaxDynamicSharedMemorySize, QKV_SMEM);
    dim3 g1(C3 / 128, TOK / 128);   // (24, 32)
    qkv_mma_kernel<<<g1, 256, QKV_SMEM>>>(bqkv);

    dim3 g2(S_ / 64, H_, B_);       // (32, 16, 2)
    rp_gemm_kernel<<<g2, 256>>>(Wr, br);

    const int smem = 4 * 64 * SMP * (int)sizeof(float);  // 69,632 B
    cudaFuncSetAttribute(attn_kernel, cudaFuncAttributeMaxDynamicSharedMemorySize, smem);
    dim3 g3(S_ / 64, H_, B_);
    attn_kernel<<<g3, 256, smem>>>(out);
}

// round 14
// speedup vs baseline: 2.4885x; 1.8449x over previous
#include <cuda_runtime.h>
#include <cuda_bf16.h>
#include <math.h>
#include <stdint.h>

#define B_   2
#define S_   2048
#define D_   1024
#define H_   16
#define HD_  64
#define R_   257
#define WIN_ 128
#define TOK  (B_*S_)    // 4096
#define C3   (3*D_)     // 3072
#define SMP  68         // smem row pad (floats) for SIMT rp kernel

// Scratch (allocation-free rule: __device__ globals)
__device__ float g_rp[(size_t)B_ * H_ * S_ * R_];                 // [b,h,i,r]
__device__ float g_qf[(size_t)B_ * H_ * S_ * HD_];                // unscaled q fp32 (for rp)
__device__ __align__(256) __nv_bfloat16 g_xhi[(size_t)TOK * D_];
__device__ __align__(256) __nv_bfloat16 g_xlo[(size_t)TOK * D_];
__device__ __align__(256) __nv_bfloat16 g_whi[(size_t)C3  * D_];
__device__ __align__(256) __nv_bfloat16 g_wlo[(size_t)C3  * D_];
// per-head bf16 hi/lo splits: [b,h,s,64]; q pre-scaled by 1/8
__device__ __align__(256) __nv_bfloat16 g_qhi[(size_t)B_*H_*S_*HD_];
__device__ __align__(256) __nv_bfloat16 g_qlo[(size_t)B_*H_*S_*HD_];
__device__ __align__(256) __nv_bfloat16 g_khi[(size_t)B_*H_*S_*HD_];
__device__ __align__(256) __nv_bfloat16 g_klo[(size_t)B_*H_*S_*HD_];
__device__ __align__(256) __nv_bfloat16 g_vhi[(size_t)B_*H_*S_*HD_];
__device__ __align__(256) __nv_bfloat16 g_vlo[(size_t)B_*H_*S_*HD_];

// ---------------------------------------------------------------------------
// Helpers
// ---------------------------------------------------------------------------
__device__ __forceinline__ uint32_t smem_u32(const void* p) {
    uint32_t a;
    asm("{ .reg .u64 t; cvta.to.shared.u64 t, %1; cvt.u32.u64 %0, t; }"
        : "=r"(a) : "l"(p));
    return a;
}
__device__ __forceinline__ void ldsm4(uint32_t* r, uint32_t a) {
    asm volatile("ldmatrix.sync.aligned.m8n8.x4.shared.b16 {%0,%1,%2,%3}, [%4];"
        : "=r"(r[0]), "=r"(r[1]), "=r"(r[2]), "=r"(r[3]) : "r"(a));
}
__device__ __forceinline__ void ldsm4t(uint32_t* r, uint32_t a) {
    asm volatile("ldmatrix.sync.aligned.m8n8.x4.trans.shared.b16 {%0,%1,%2,%3}, [%4];"
        : "=r"(r[0]), "=r"(r[1]), "=r"(r[2]), "=r"(r[3]) : "r"(a));
}
__device__ __forceinline__ void mma16816(float* d, const uint32_t* a, const uint32_t* b) {
    asm volatile(
        "mma.sync.aligned.m16n8k16.row.col.f32.bf16.bf16.f32 "
        "{%0,%1,%2,%3}, {%4,%5,%6,%7}, {%8,%9}, {%0,%1,%2,%3};"
        : "+f"(d[0]), "+f"(d[1]), "+f"(d[2]), "+f"(d[3])
        : "r"(a[0]), "r"(a[1]), "r"(a[2]), "r"(a[3]), "r"(b[0]), "r"(b[1]));
}
// e^x on FMA/ALU pipes only (no MUFU). Valid for x <= 0 (softmax args).
__device__ __forceinline__ float fexp(float x) {
    float t = fmaxf(x * 1.4426950408889634f, -126.0f);
    float z = t + 12582912.0f;                       // round-to-nearest (2^23*1.5)
    int   i = __float_as_int(z) - 0x4B400000;
    float f = t - (z - 12582912.0f);                 // f in [-0.5, 0.5]
    float p = 1.3333558e-3f;
    p = fmaf(p, f, 9.6181291e-3f);
    p = fmaf(p, f, 5.5504109e-2f);
    p = fmaf(p, f, 2.4022651e-1f);
    p = fmaf(p, f, 6.9314718e-1f);
    p = fmaf(p, f, 1.0f);
    return p * __int_as_float((i + 127) << 23);
}
// split two fp32 into packed bf16x2 hi and lo words
__device__ __forceinline__ void split2(float a, float b, uint32_t& hi, uint32_t& lo) {
    __nv_bfloat16 ha = __float2bfloat16(a), hb = __float2bfloat16(b);
    __nv_bfloat16 la = __float2bfloat16(a - __bfloat162float(ha));
    __nv_bfloat16 lb = __float2bfloat16(b - __bfloat162float(hb));
    __nv_bfloat162 h2; h2.x = ha; h2.y = hb;
    __nv_bfloat162 l2; l2.x = la; l2.y = lb;
    hi = *(uint32_t*)&h2; lo = *(uint32_t*)&l2;
}

// ---------------------------------------------------------------------------
// Kernel 0: split fp32 -> bf16 hi/lo pair
// ---------------------------------------------------------------------------
__global__ __launch_bounds__(256) void split_bf16_kernel(
    const float4* __restrict__ src, __nv_bfloat162* __restrict__ hi,
    __nv_bfloat162* __restrict__ lo, int n4)
{
    int i = blockIdx.x * 256 + threadIdx.x;
    if (i >= n4) return;
    float4 v = src[i];
    uint32_t h0, l0, h1, l1;
    split2(v.x, v.y, h0, l0);
    split2(v.z, v.w, h1, l1);
    ((uint32_t*)hi)[i * 2 + 0] = h0; ((uint32_t*)hi)[i * 2 + 1] = h1;
    ((uint32_t*)lo)[i * 2 + 0] = l0; ((uint32_t*)lo)[i * 2 + 1] = l1;
}

// ---------------------------------------------------------------------------
// Kernel 1: QKV GEMM via mma.sync (bf16x3 split). Epilogue writes per-head
// bf16 hi/lo q (x1/8), k, v buffers + unscaled fp32 q for rp.
// ---------------------------------------------------------------------------
#define KC     64
#define SROW   144
#define TILEB  (128 * SROW)
#define OFF_AH 0
#define OFF_AL (1 * TILEB)
#define OFF_BH (2 * TILEB)
#define OFF_BL (3 * TILEB)
#define QKV_SMEM (4 * TILEB)           // 73,728 B

__global__ __launch_bounds__(256, 2) void qkv_mma_kernel(const float* __restrict__ bias)
{
    extern __shared__ char smem[];
    const uint32_t sbase = smem_u32(smem);
    const int tid  = threadIdx.x;
    const int wid  = tid >> 5, lane = tid & 31;
    const int wm   = wid & 3;
    const int wn   = wid >> 2;
    const int n0   = blockIdx.x * 128;
    const int m0   = blockIdx.y * 128;

    const __nv_bfloat16* Ah = g_xhi + (size_t)m0 * D_;
    const __nv_bfloat16* Al = g_xlo + (size_t)m0 * D_;
    const __nv_bfloat16* Bh = g_whi + (size_t)n0 * D_;
    const __nv_bfloat16* Bl = g_wlo + (size_t)n0 * D_;

    const uint32_t a_row  = (uint32_t)(wm * 32 + ((lane >> 3) & 1) * 8 + (lane & 7));
    const uint32_t a_colb = (uint32_t)((lane >> 4) * 16);
    const uint32_t aAH = sbase + OFF_AH + a_row * SROW + a_colb;
    const uint32_t aAL = sbase + OFF_AL + a_row * SROW + a_colb;
    const uint32_t b_row  = (uint32_t)(wn * 64 + ((lane >> 4) << 3) + (lane & 7));
    const uint32_t b_colb = (uint32_t)(((lane >> 3) & 1) * 16);
    const uint32_t bBH = sbase + OFF_BH + b_row * SROW + b_colb;
    const uint32_t bBL = sbase + OFF_BL + b_row * SROW + b_colb;

    float acc[2][8][4];
#pragma unroll
    for (int mt = 0; mt < 2; mt++)
#pragma unroll
        for (int nt = 0; nt < 8; nt++)
#pragma unroll
            for (int e = 0; e < 4; e++) acc[mt][nt][e] = 0.0f;

    const int lrow = tid >> 3;
    const int lc8  = tid & 7;

    for (int ch = 0; ch < D_ / KC; ch++) {
        const int k0 = ch * KC;
        __syncthreads();
#pragma unroll
        for (int t = 0; t < 4; t++) {
            int row = lrow + t * 32;
            uint32_t so = (uint32_t)(row * SROW + lc8 * 16);
            size_t gsrc = (size_t)row * D_ + k0 + lc8 * 8;
            *(uint4*)(smem + OFF_AH + so) = *(const uint4*)(Ah + gsrc);
            *(uint4*)(smem + OFF_AL + so) = *(const uint4*)(Al + gsrc);
            *(uint4*)(smem + OFF_BH + so) = *(const uint4*)(Bh + gsrc);
            *(uint4*)(smem + OFF_BL + so) = *(const uint4*)(Bl + gsrc);
        }
        __syncthreads();

#pragma unroll
        for (int ks = 0; ks < 4; ks++) {
            uint32_t aH[2][4], aL[2][4];
            ldsm4(aH[0], aAH + ks * 32);
            ldsm4(aH[1], aAH + 16 * SROW + ks * 32);
            ldsm4(aL[0], aAL + ks * 32);
            ldsm4(aL[1], aAL + 16 * SROW + ks * 32);
#pragma unroll
            for (int ntp = 0; ntp < 4; ntp++) {
                uint32_t bH[4], bL[4];
                ldsm4(bH, bBH + ntp * (16 * SROW) + ks * 32);
                ldsm4(bL, bBL + ntp * (16 * SROW) + ks * 32);
#pragma unroll
                for (int mt = 0; mt < 2; mt++) {
#pragma unroll
                    for (int ntl = 0; ntl < 2; ntl++) {
                        float* d = acc[mt][ntp * 2 + ntl];
                        mma16816(d, aH[mt], bH + ntl * 2);
                        mma16816(d, aH[mt], bL + ntl * 2);
                        mma16816(d, aL[mt], bH + ntl * 2);
                    }
                }
            }
        }
    }

    // Epilogue: bias add, route to per-head q/k/v bf16 hi/lo buffers (+ fp32 q)
    const int g = lane >> 2, tq = lane & 3;
#pragma unroll
    for (int mt = 0; mt < 2; mt++) {
        const int t0 = m0 + wm * 32 + mt * 16 + g;
#pragma unroll
        for (int nt = 0; nt < 8; nt++) {
            const int col = n0 + wn * 64 + nt * 8 + tq * 2;
            const int h     = col / 192;
            const int r     = col - h * 192;
            const int which = r >> 6;
            const int dim   = r & 63;
            float2 bv = *(const float2*)(bias + col);
            float xv[2][2];
            xv[0][0] = acc[mt][nt][0] + bv.x; xv[0][1] = acc[mt][nt][1] + bv.y;
            xv[1][0] = acc[mt][nt][2] + bv.x; xv[1][1] = acc[mt][nt][3] + bv.y;
#pragma unroll
            for (int rr = 0; rr < 2; rr++) {
                const int tok = t0 + rr * 8;
                const int bb = tok >> 11, ss = tok & (S_ - 1);
                const size_t base = (((size_t)bb * H_ + h) * S_ + ss) * HD_ + dim;
                float xa = xv[rr][0], xb = xv[rr][1];
                uint32_t hi, lo;
                if (which == 0) {
                    float2 qf; qf.x = xa; qf.y = xb;
                    *(float2*)(g_qf + base) = qf;
                    split2(xa * 0.125f, xb * 0.125f, hi, lo);
                    *(uint32_t*)(g_qhi + base) = hi;
                    *(uint32_t*)(g_qlo + base) = lo;
                } else if (which == 1) {
                    split2(xa, xb, hi, lo);
                    *(uint32_t*)(g_khi + base) = hi;
                    *(uint32_t*)(g_klo + base) = lo;
                } else {
                    split2(xa, xb, hi, lo);
                    *(uint32_t*)(g_vhi + base) = hi;
                    *(uint32_t*)(g_vlo + base) = lo;
                }
            }
        }
    }
}

// ---------------------------------------------------------------------------
// Kernel 2: rp[b,h,i,r] = sum_k q[b,h,i,k] * Wr[r,k] + br[r]   (unscaled q)
// ---------------------------------------------------------------------------
__global__ __launch_bounds__(256) void rp_gemm_kernel(
    const float* __restrict__ Wr, const float* __restrict__ br)
{
    __shared__ float Qs[64 * SMP];
    __shared__ float Ws[64 * SMP];
    const int tid = threadIdx.x;
    const int i0 = blockIdx.x * 64;
    const int h  = blockIdx.y;
    const int b  = blockIdx.z;
    const int tr = tid >> 4, tc = tid & 15;
    const size_t qbase = ((size_t)(b * H_ + h) * S_ + i0) * HD_;

#pragma unroll
    for (int t = 0; t < 4; t++) {
        int idx = tid + t * 256;
        int row = idx >> 4;
        int k4  = (idx & 15) << 2;
        float4 v = *(const float4*)(g_qf + qbase + (size_t)row * HD_ + k4);
        Qs[(k4 + 0) * SMP + row] = v.x;
        Qs[(k4 + 1) * SMP + row] = v.y;
        Qs[(k4 + 2) * SMP + row] = v.z;
        Qs[(k4 + 3) * SMP + row] = v.w;
    }

    float* rpb = g_rp + ((size_t)(b * H_ + h) * S_ + i0) * R_;

    for (int r0 = 0; r0 < R_; r0 += 64) {
        __syncthreads();
#pragma unroll
        for (int t = 0; t < 4; t++) {
            int idx = tid + t * 256;
            int rl  = idx >> 4;
            int k4  = (idx & 15) << 2;
            float4 v = make_float4(0.f, 0.f, 0.f, 0.f);
            if (r0 + rl < R_) v = *(const float4*)(Wr + (size_t)(r0 + rl) * HD_ + k4);
            Ws[(k4 + 0) * SMP + rl] = v.x;
            Ws[(k4 + 1) * SMP + rl] = v.y;
            Ws[(k4 + 2) * SMP + rl] = v.z;
            Ws[(k4 + 3) * SMP + rl] = v.w;
        }
        __syncthreads();

        float acc[4][4];
#pragma unroll
        for (int i = 0; i < 4; i++)
#pragma unroll
            for (int j = 0; j < 4; j++) acc[i][j] = 0.0f;

#pragma unroll 8
        for (int k = 0; k < 64; k++) {
            float4 qa = *(const float4*)(Qs + k * SMP + tr * 4);
            float4 wb = *(const float4*)(Ws + k * SMP + tc * 4);
            float a[4] = {qa.x, qa.y, qa.z, qa.w};
            float w[4] = {wb.x, wb.y, wb.z, wb.w};
#pragma unroll
            for (int i = 0; i < 4; i++)
#pragma unroll
                for (int j = 0; j < 4; j++) acc[i][j] += a[i] * w[j];
        }

#pragma unroll
        for (int i = 0; i < 4; i++) {
            int irow = tr * 4 + i;
#pragma unroll
            for (int j = 0; j < 4; j++) {
                int r = r0 + tc * 4 + j;
                if (r < R_) rpb[(size_t)irow * R_ + r] = acc[i][j] + br[r];
            }
        }
    }
}

// ---------------------------------------------------------------------------
// Kernel 3: flash attention on tensor cores (bf16x3 split QK^T and PV),
// software exp (no MUFU), clip-hoisted rel-pos bias.
// CTA = 128 queries of one (b,h); 8 warps x 16 rows; key tiles of 64.
// P-split + PV fused per 16-key chunk to keep live registers low (no forced
// occupancy, no spill cliff).
// ---------------------------------------------------------------------------
#define AT_KH  0
#define AT_KL  9216
#define AT_VH  18432
#define AT_VL  27648

__global__ __launch_bounds__(256) void attn_mma_kernel(float* __restrict__ out)
{
    __shared__ __align__(16) char smem[4 * 64 * SROW];   // 36,864 B
    const uint32_t sb = smem_u32(smem);
    const int tid = threadIdx.x, wid = tid >> 5, lane = tid & 31;
    const int g = lane >> 2, tq = lane & 3;
    const int q0 = blockIdx.x * 128;
    const int h  = blockIdx.y, b = blockIdx.z;
    const size_t hb64 = ((size_t)(b * H_ + h)) * S_ * HD_;

    // ---- stage Q (hi at 0, lo at 18432), build register fragments ----
    {
        const __nv_bfloat16* qh = g_qhi + hb64 + (size_t)q0 * HD_;
        const __nv_bfloat16* ql = g_qlo + hb64 + (size_t)q0 * HD_;
#pragma unroll
        for (int t = 0; t < 4; t++) {
            int idx = tid + t * 256;
            int row = idx >> 3, c8 = idx & 7;
            *(uint4*)(smem + row * SROW + c8 * 16)         = *(const uint4*)(qh + row * HD_ + c8 * 8);
            *(uint4*)(smem + 18432 + row * SROW + c8 * 16) = *(const uint4*)(ql + row * HD_ + c8 * 8);
        }
    }
    __syncthreads();
    uint32_t qh[4][4], ql[4][4];
    {
        const uint32_t qa = sb + (uint32_t)((wid * 16 + ((lane >> 3) & 1) * 8 + (lane & 7)) * SROW
                                            + (lane >> 4) * 16);
#pragma unroll
        for (int ks = 0; ks < 4; ks++) {
            ldsm4(qh[ks], qa + ks * 32);
            ldsm4(ql[ks], qa + 18432 + ks * 32);
        }
    }
    __syncthreads();

    float oacc[8][4];
#pragma unroll
    for (int nt = 0; nt < 8; nt++)
#pragma unroll
        for (int e = 0; e < 4; e++) oacc[nt][e] = 0.0f;
    float mrow[2] = {-1e30f, -1e30f}, lrow[2] = {0.0f, 0.0f};

    const int i1 = q0 + wid * 16 + g;   // global query rows of this lane
    const int i2 = i1 + 8;
    const float* rp1 = g_rp + ((size_t)(b * H_ + h) * S_ + i1) * R_;
    const float* rp2 = rp1 + (size_t)8 * R_;
    const float rp1_lo = __ldg(rp1), rp1_hi = __ldg(rp1 + 2 * WIN_);
    const float rp2_lo = __ldg(rp2), rp2_hi = __ldg(rp2 + 2 * WIN_);

    const __nv_bfloat16* kh = g_khi + hb64;
    const __nv_bfloat16* kl = g_klo + hb64;
    const __nv_bfloat16* vh = g_vhi + hb64;
    const __nv_bfloat16* vl = g_vlo + hb64;

    const uint32_t koff = (uint32_t)((((lane >> 4) << 3) + (lane & 7)) * SROW + ((lane >> 3) & 1) * 16);
    const uint32_t voff = (uint32_t)((((lane >> 3) & 1) * 8 + (lane & 7)) * SROW + (lane >> 4) * 16);

    for (int kt = 0; kt < S_ / 64; kt++) {
        const int kt64 = kt * 64;
        // load K/V hi/lo tiles
#pragma unroll
        for (int t = 0; t < 2; t++) {
            int idx = tid + t * 256;
            int row = idx >> 3, c8 = idx & 7;
            size_t src = (size_t)(kt64 + row) * HD_ + c8 * 8;
            int dst = row * SROW + c8 * 16;
            *(uint4*)(smem + AT_KH + dst) = *(const uint4*)(kh + src);
            *(uint4*)(smem + AT_KL + dst) = *(const uint4*)(kl + src);
            *(uint4*)(smem + AT_VH + dst) = *(const uint4*)(vh + src);
            *(uint4*)(smem + AT_VL + dst) = *(const uint4*)(vl + src);
        }
        __syncthreads();

        // ---- scores S = Q.K^T (3-way split) ----
        float sacc[8][4];
#pragma unroll
        for (int nt = 0; nt < 8; nt++)
#pragma unroll
            for (int e = 0; e < 4; e++) sacc[nt][e] = 0.0f;
#pragma unroll
        for (int ks = 0; ks < 4; ks++) {
#pragma unroll
            for (int ntp = 0; ntp < 4; ntp++) {
                uint32_t bH[4], bL[4];
                ldsm4(bH, sb + AT_KH + ntp * (16 * SROW) + ks * 32 + koff);
                ldsm4(bL, sb + AT_KL + ntp * (16 * SROW) + ks * 32 + koff);
#pragma unroll
                for (int ntl = 0; ntl < 2; ntl++) {
                    float* d = sacc[ntp * 2 + ntl];
                    mma16816(d, qh[ks], bH + ntl * 2);
                    mma16816(d, qh[ks], bL + ntl * 2);
                    mma16816(d, ql[ks], bH + ntl * 2);
                }
            }
        }

        // ---- rel-pos bias: hoisted constants for fully-clipped tiles ----
        if (i1 >= kt64 + 191) {
#pragma unroll
            for (int nt = 0; nt < 8; nt++) { sacc[nt][0] += rp1_lo; sacc[nt][1] += rp1_lo; }
        } else if (i1 + WIN_ <= kt64) {
#pragma unroll
            for (int nt = 0; nt < 8; nt++) { sacc[nt][0] += rp1_hi; sacc[nt][1] += rp1_hi; }
        } else {
#pragma unroll
            for (int nt = 0; nt < 8; nt++)
#pragma unroll
                for (int e = 0; e < 2; e++) {
                    int off = kt64 + nt * 8 + tq * 2 + e - i1;
                    off = off < -WIN_ ? -WIN_ : (off > WIN_ ? WIN_ : off);
                    sacc[nt][e] += __ldg(rp1 + off + WIN_);
                }
        }
        if (i2 >= kt64 + 191) {
#pragma unroll
            for (int nt = 0; nt < 8; nt++) { sacc[nt][2] += rp2_lo; sacc[nt][3] += rp2_lo; }
        } else if (i2 + WIN_ <= kt64) {
#pragma unroll
            for (int nt = 0; nt < 8; nt++) { sacc[nt][2] += rp2_hi; sacc[nt][3] += rp2_hi; }
        } else {
#pragma unroll
            for (int nt = 0; nt < 8; nt++)
#pragma unroll
                for (int e = 0; e < 2; e++) {
                    int off = kt64 + nt * 8 + tq * 2 + e - i2;
                    off = off < -WIN_ ? -WIN_ : (off > WIN_ ? WIN_ : off);
                    sacc[nt][2 + e] += __ldg(rp2 + off + WIN_);
                }
        }

        // ---- online softmax (rows g, g+8; quad = lanes sharing a row) ----
        float mx1 = -1e30f, mx2 = -1e30f;
#pragma unroll
        for (int nt = 0; nt < 8; nt++) {
            mx1 = fmaxf(mx1, fmaxf(sacc[nt][0], sacc[nt][1]));
            mx2 = fmaxf(mx2, fmaxf(sacc[nt][2], sacc[nt][3]));
        }
        mx1 = fmaxf(mx1, __shfl_xor_sync(0xffffffffu, mx1, 1));
        mx1 = fmaxf(mx1, __shfl_xor_sync(0xffffffffu, mx1, 2));
        mx2 = fmaxf(mx2, __shfl_xor_sync(0xffffffffu, mx2, 1));
        mx2 = fmaxf(mx2, __shfl_xor_sync(0xffffffffu, mx2, 2));
        float mn1 = fmaxf(mrow[0], mx1), mn2 = fmaxf(mrow[1], mx2);
        float al1 = fexp(mrow[0] - mn1), al2 = fexp(mrow[1] - mn2);
        mrow[0] = mn1; mrow[1] = mn2;
        float sum1 = 0.0f, sum2 = 0.0f;
#pragma unroll
        for (int nt = 0; nt < 8; nt++) {
            float p0 = fexp(sacc[nt][0] - mn1), p1 = fexp(sacc[nt][1] - mn1);
            float p2 = fexp(sacc[nt][2] - mn2), p3 = fexp(sacc[nt][3] - mn2);
            sacc[nt][0] = p0; sacc[nt][1] = p1; sacc[nt][2] = p2; sacc[nt][3] = p3;
            sum1 += p0 + p1; sum2 += p2 + p3;
        }
        sum1 += __shfl_xor_sync(0xffffffffu, sum1, 1);
        sum1 += __shfl_xor_sync(0xffffffffu, sum1, 2);
        sum2 += __shfl_xor_sync(0xffffffffu, sum2, 1);
        sum2 += __shfl_xor_sync(0xffffffffu, sum2, 2);
        lrow[0] = lrow[0] * al1 + sum1;
        lrow[1] = lrow[1] * al2 + sum2;
#pragma unroll
        for (int nt = 0; nt < 8; nt++) {
            oacc[nt][0] *= al1; oacc[nt][1] *= al1;
            oacc[nt][2] *= al2; oacc[nt][3] *= al2;
        }

        // ---- O += P.V per 16-key chunk: split P, then MMA (low live regs) ----
#pragma unroll
        for (int kc = 0; kc < 4; kc++) {
            uint32_t ph[4], pl[4];
            split2(sacc[2*kc][0],   sacc[2*kc][1],   ph[0], pl[0]);
            split2(sacc[2*kc][2],   sacc[2*kc][3],   ph[1], pl[1]);
            split2(sacc[2*kc+1][0], sacc[2*kc+1][1], ph[2], pl[2]);
            split2(sacc[2*kc+1][2], sacc[2*kc+1][3], ph[3], pl[3]);
#pragma unroll
            for (int ndp = 0; ndp < 4; ndp++) {
                uint32_t vH[4], vL[4];
                ldsm4t(vH, sb + AT_VH + kc * (16 * SROW) + ndp * 32 + voff);
                ldsm4t(vL, sb + AT_VL + kc * (16 * SROW) + ndp * 32 + voff);
#pragma unroll
                for (int ntl = 0; ntl < 2; ntl++) {
                    float* d = oacc[ndp * 2 + ntl];
                    mma16816(d, ph, vH + ntl * 2);
                    mma16816(d, ph, vL + ntl * 2);
                    mma16816(d, pl, vH + ntl * 2);
                }
            }
        }
        __syncthreads();
    }

    // ---- epilogue ----
    const float inv1 = 1.0f / lrow[0], inv2 = 1.0f / lrow[1];
#pragma unroll
    for (int nt = 0; nt < 8; nt++) {
        const int col = h * HD_ + nt * 8 + tq * 2;
        float2 o1; o1.x = oacc[nt][0] * inv1; o1.y = oacc[nt][1] * inv1;
        float2 o2; o2.x = oacc[nt][2] * inv2; o2.y = oacc[nt][3] * inv2;
        *(float2*)(out + (size_t)(b * S_ + i1) * D_ + col) = o1;
        *(float2*)(out + (size_t)(b * S_ + i2) * D_ + col) = o2;
    }
}

// ---------------------------------------------------------------------------
extern "C" void kernel_launch(void* const* d_in, const int* in_sizes, int n_in,
                              void* d_out, int out_size)
{
    const float* x    = (const float*)d_in[0];
    const float* Wqkv = (const float*)d_in[1];
    const float* bqkv = (const float*)d_in[2];
    const float* Wr   = (const float*)d_in[3];
    const float* br   = (const float*)d_in[4];
    float* out = (float*)d_out;

    __nv_bfloat162 *xhi, *xlo, *whi, *wlo;
    cudaGetSymbolAddress((void**)&xhi, g_xhi);
    cudaGetSymbolAddress((void**)&xlo, g_xlo);
    cudaGetSymbolAddress((void**)&whi, g_whi);
    cudaGetSymbolAddress((void**)&wlo, g_wlo);

    split_bf16_kernel<<<(TOK * D_ / 4 + 255) / 256, 256>>>(
        (const float4*)x, xhi, xlo, TOK * D_ / 4);
    split_bf16_kernel<<<(C3 * D_ / 4 + 255) / 256, 256>>>(
        (const float4*)Wqkv, whi, wlo, C3 * D_ / 4);

    cudaFuncSetAttribute(qkv_mma_kernel,
                         cudaFuncAttributeMaxDynamicSharedMemorySize, QKV_SMEM);
    dim3 g1(C3 / 128, TOK / 128);   // (24, 32)
    qkv_mma_kernel<<<g1, 256, QKV_SMEM>>>(bqkv);

    dim3 g2(S_ / 64, H_, B_);       // (32, 16, 2)
    rp_gemm_kernel<<<g2, 256>>>(Wr, br);

    dim3 g3(S_ / 128, H_, B_);      // (16, 16, 2)
    attn_mma_kernel<<<g3, 256>>>(out);
}

// round 15
// speedup vs baseline: 2.8463x; 1.1438x over previous
#include <cuda_runtime.h>
#include <cuda_bf16.h>
#include <math.h>
#include <stdint.h>

#define B_   2
#define S_   2048
#define D_   1024
#define H_   16
#define HD_  64
#define R_   257
#define RP   272        // padded rp row stride (17 n-tiles of 16)
#define WIN_ 128
#define TOK  (B_*S_)    // 4096
#define C3   (3*D_)     // 3072

// Scratch (allocation-free rule: __device__ globals)
__device__ float g_rp[(size_t)B_ * H_ * S_ * RP];                 // [b,h,i,r] padded
__device__ __align__(256) __nv_bfloat16 g_xhi[(size_t)TOK * D_];
__device__ __align__(256) __nv_bfloat16 g_xlo[(size_t)TOK * D_];
__device__ __align__(256) __nv_bfloat16 g_whi[(size_t)C3  * D_];
__device__ __align__(256) __nv_bfloat16 g_wlo[(size_t)C3  * D_];
__device__ __align__(256) __nv_bfloat16 g_wr8h[272 * HD_];        // 8*Wr hi (padded rows)
__device__ __align__(256) __nv_bfloat16 g_wr8l[272 * HD_];        // 8*Wr lo
// per-head bf16 hi/lo splits: [b,h,s,64]; q pre-scaled by 1/8
__device__ __align__(256) __nv_bfloat16 g_qhi[(size_t)B_*H_*S_*HD_];
__device__ __align__(256) __nv_bfloat16 g_qlo[(size_t)B_*H_*S_*HD_];
__device__ __align__(256) __nv_bfloat16 g_khi[(size_t)B_*H_*S_*HD_];
__device__ __align__(256) __nv_bfloat16 g_klo[(size_t)B_*H_*S_*HD_];
__device__ __align__(256) __nv_bfloat16 g_vhi[(size_t)B_*H_*S_*HD_];
__device__ __align__(256) __nv_bfloat16 g_vlo[(size_t)B_*H_*S_*HD_];

// ---------------------------------------------------------------------------
// Helpers
// ---------------------------------------------------------------------------
__device__ __forceinline__ uint32_t smem_u32(const void* p) {
    uint32_t a;
    asm("{ .reg .u64 t; cvta.to.shared.u64 t, %1; cvt.u32.u64 %0, t; }"
        : "=r"(a) : "l"(p));
    return a;
}
__device__ __forceinline__ void ldsm4(uint32_t* r, uint32_t a) {
    asm volatile("ldmatrix.sync.aligned.m8n8.x4.shared.b16 {%0,%1,%2,%3}, [%4];"
        : "=r"(r[0]), "=r"(r[1]), "=r"(r[2]), "=r"(r[3]) : "r"(a));
}
__device__ __forceinline__ void ldsm4t(uint32_t* r, uint32_t a) {
    asm volatile("ldmatrix.sync.aligned.m8n8.x4.trans.shared.b16 {%0,%1,%2,%3}, [%4];"
        : "=r"(r[0]), "=r"(r[1]), "=r"(r[2]), "=r"(r[3]) : "r"(a));
}
__device__ __forceinline__ void mma16816(float* d, const uint32_t* a, const uint32_t* b) {
    asm volatile(
        "mma.sync.aligned.m16n8k16.row.col.f32.bf16.bf16.f32 "
        "{%0,%1,%2,%3}, {%4,%5,%6,%7}, {%8,%9}, {%0,%1,%2,%3};"
        : "+f"(d[0]), "+f"(d[1]), "+f"(d[2]), "+f"(d[3])
        : "r"(a[0]), "r"(a[1]), "r"(a[2]), "r"(a[3]), "r"(b[0]), "r"(b[1]));
}
__device__ __forceinline__ void cpasync16(uint32_t dst, const void* src) {
    asm volatile("cp.async.cg.shared.global [%0], [%1], 16;" :: "r"(dst), "l"(src));
}
#define CP_COMMIT() asm volatile("cp.async.commit_group;" ::: "memory")
#define CP_WAIT1()  asm volatile("cp.async.wait_group 1;"  ::: "memory")

// e^x on FMA/ALU pipes only (no MUFU). Valid for x <= 0 (softmax args).
__device__ __forceinline__ float fexp(float x) {
    float t = fmaxf(x * 1.4426950408889634f, -126.0f);
    float z = t + 12582912.0f;                       // round-to-nearest (2^23*1.5)
    int   i = __float_as_int(z) - 0x4B400000;
    float f = t - (z - 12582912.0f);                 // f in [-0.5, 0.5]
    float p = 1.3333558e-3f;
    p = fmaf(p, f, 9.6181291e-3f);
    p = fmaf(p, f, 5.5504109e-2f);
    p = fmaf(p, f, 2.4022651e-1f);
    p = fmaf(p, f, 6.9314718e-1f);
    p = fmaf(p, f, 1.0f);
    return p * __int_as_float((i + 127) << 23);
}
// split two fp32 into packed bf16x2 hi and lo words
__device__ __forceinline__ void split2(float a, float b, uint32_t& hi, uint32_t& lo) {
    __nv_bfloat16 ha = __float2bfloat16(a), hb = __float2bfloat16(b);
    __nv_bfloat16 la = __float2bfloat16(a - __bfloat162float(ha));
    __nv_bfloat16 lb = __float2bfloat16(b - __bfloat162float(hb));
    __nv_bfloat162 h2; h2.x = ha; h2.y = hb;
    __nv_bfloat162 l2; l2.x = la; l2.y = lb;
    hi = *(uint32_t*)&h2; lo = *(uint32_t*)&l2;
}

// ---------------------------------------------------------------------------
// Kernel 0: split fp32 -> bf16 hi/lo pair
// ---------------------------------------------------------------------------
__global__ __launch_bounds__(256) void split_bf16_kernel(
    const float4* __restrict__ src, __nv_bfloat162* __restrict__ hi,
    __nv_bfloat162* __restrict__ lo, int n4)
{
    int i = blockIdx.x * 256 + threadIdx.x;
    if (i >= n4) return;
    float4 v = src[i];
    uint32_t h0, l0, h1, l1;
    split2(v.x, v.y, h0, l0);
    split2(v.z, v.w, h1, l1);
    ((uint32_t*)hi)[i * 2 + 0] = h0; ((uint32_t*)hi)[i * 2 + 1] = h1;
    ((uint32_t*)lo)[i * 2 + 0] = l0; ((uint32_t*)lo)[i * 2 + 1] = l1;
}

// Kernel 0b: split 8*Wr into padded [272][64] bf16 hi/lo
__global__ __launch_bounds__(256) void split_wr8_kernel(const float* __restrict__ Wr)
{
    int i = blockIdx.x * 256 + threadIdx.x;     // pair index
    if (i >= 272 * HD_ / 2) return;
    int r = i >> 5;                             // 32 pairs per row
    int c = (i & 31) << 1;
    float a = 0.0f, b = 0.0f;
    if (r < R_) { a = Wr[r * HD_ + c] * 8.0f; b = Wr[r * HD_ + c + 1] * 8.0f; }
    uint32_t hi, lo;
    split2(a, b, hi, lo);
    ((uint32_t*)g_wr8h)[i] = hi;
    ((uint32_t*)g_wr8l)[i] = lo;
}

// ---------------------------------------------------------------------------
// Kernel 1: QKV GEMM via mma.sync (bf16x3 split), cp.async 2-stage pipeline.
// CTA tile 128x128, 8 warps (4x2), warp 32x64. K in 32 chunks of 32.
// Epilogue writes per-head bf16 hi/lo q (x1/8), k, v.
// ---------------------------------------------------------------------------
#define SROW   144                     // attn/rp smem row bytes (64 bf16 + pad)
#define KC2    32
#define SROW2  80                      // qkv smem row bytes (32 bf16 + pad)
#define T2     (128 * SROW2)           // 10,240
#define O2_AH  0
#define O2_AL  (1 * T2)
#define O2_BH  (2 * T2)
#define O2_BL  (3 * T2)
#define STG2   (4 * T2)                // 40,960 per stage
#define QKV_SMEM (2 * STG2)            // 81,920

__global__ __launch_bounds__(256, 2) void qkv_mma_kernel(const float* __restrict__ bias)
{
    extern __shared__ char smem[];
    const uint32_t sbase = smem_u32(smem);
    const int tid  = threadIdx.x;
    const int wid  = tid >> 5, lane = tid & 31;
    const int wm   = wid & 3;
    const int wn   = wid >> 2;
    const int n0   = blockIdx.x * 128;
    const int m0   = blockIdx.y * 128;

    const __nv_bfloat16* Ah = g_xhi + (size_t)m0 * D_;
    const __nv_bfloat16* Al = g_xlo + (size_t)m0 * D_;
    const __nv_bfloat16* Bh = g_whi + (size_t)n0 * D_;
    const __nv_bfloat16* Bl = g_wlo + (size_t)n0 * D_;

    const uint32_t a_ro  = (uint32_t)((wm * 32 + ((lane >> 3) & 1) * 8 + (lane & 7)) * SROW2
                                      + (lane >> 4) * 16);
    const uint32_t b_ro  = (uint32_t)((wn * 64 + ((lane >> 4) << 3) + (lane & 7)) * SROW2
                                      + ((lane >> 3) & 1) * 16);

    float acc[2][8][4];
#pragma unroll
    for (int mt = 0; mt < 2; mt++)
#pragma unroll
        for (int nt = 0; nt < 8; nt++)
#pragma unroll
            for (int e = 0; e < 4; e++) acc[mt][nt][e] = 0.0f;

    auto issue = [&](int ch, int s) {
        const uint32_t sb = sbase + s * STG2;
#pragma unroll
        for (int t = 0; t < 2; t++) {
            int idx = tid + t * 256;
            int row = idx >> 2, c16 = idx & 3;
            uint32_t so = (uint32_t)(row * SROW2 + c16 * 16);
            size_t goff = (size_t)row * D_ + ch * KC2 + c16 * 8;
            cpasync16(sb + O2_AH + so, Ah + goff);
            cpasync16(sb + O2_AL + so, Al + goff);
            cpasync16(sb + O2_BH + so, Bh + goff);
            cpasync16(sb + O2_BL + so, Bl + goff);
        }
    };

    issue(0, 0);
    CP_COMMIT();

    for (int ch = 0; ch < D_ / KC2; ch++) {
        const int s = ch & 1;
        const uint32_t sbs = sbase + s * STG2;
        if (ch + 1 < D_ / KC2) issue(ch + 1, s ^ 1);
        CP_COMMIT();
        CP_WAIT1();
        __syncthreads();

#pragma unroll
        for (int ks = 0; ks < 2; ks++) {
            uint32_t aH[2][4], aL[2][4];
            ldsm4(aH[0], sbs + O2_AH + a_ro + ks * 32);
            ldsm4(aH[1], sbs + O2_AH + a_ro + 16 * SROW2 + ks * 32);
            ldsm4(aL[0], sbs + O2_AL + a_ro + ks * 32);
            ldsm4(aL[1], sbs + O2_AL + a_ro + 16 * SROW2 + ks * 32);
#pragma unroll
            for (int ntp = 0; ntp < 4; ntp++) {
                uint32_t bH[4], bL[4];
                ldsm4(bH, sbs + O2_BH + b_ro + ntp * (16 * SROW2) + ks * 32);
                ldsm4(bL, sbs + O2_BL + b_ro + ntp * (16 * SROW2) + ks * 32);
#pragma unroll
                for (int mt = 0; mt < 2; mt++) {
#pragma unroll
                    for (int ntl = 0; ntl < 2; ntl++) {
                        float* d = acc[mt][ntp * 2 + ntl];
                        mma16816(d, aH[mt], bH + ntl * 2);
                        mma16816(d, aH[mt], bL + ntl * 2);
                        mma16816(d, aL[mt], bH + ntl * 2);
                    }
                }
            }
        }
        __syncthreads();
    }

    // Epilogue: bias add, route to per-head q/k/v bf16 hi/lo buffers
    const int g = lane >> 2, tq = lane & 3;
#pragma unroll
    for (int mt = 0; mt < 2; mt++) {
        const int t0 = m0 + wm * 32 + mt * 16 + g;
#pragma unroll
        for (int nt = 0; nt < 8; nt++) {
            const int col = n0 + wn * 64 + nt * 8 + tq * 2;
            const int h     = col / 192;
            const int r     = col - h * 192;
            const int which = r >> 6;
            const int dim   = r & 63;
            float2 bv = *(const float2*)(bias + col);
            float xv[2][2];
            xv[0][0] = acc[mt][nt][0] + bv.x; xv[0][1] = acc[mt][nt][1] + bv.y;
            xv[1][0] = acc[mt][nt][2] + bv.x; xv[1][1] = acc[mt][nt][3] + bv.y;
#pragma unroll
            for (int rr = 0; rr < 2; rr++) {
                const int tok = t0 + rr * 8;
                const int bb = tok >> 11, ss = tok & (S_ - 1);
                const size_t base = (((size_t)bb * H_ + h) * S_ + ss) * HD_ + dim;
                float xa = xv[rr][0], xb = xv[rr][1];
                uint32_t hi, lo;
                if (which == 0) {
                    split2(xa * 0.125f, xb * 0.125f, hi, lo);
                    *(uint32_t*)(g_qhi + base) = hi;
                    *(uint32_t*)(g_qlo + base) = lo;
                } else if (which == 1) {
                    split2(xa, xb, hi, lo);
                    *(uint32_t*)(g_khi + base) = hi;
                    *(uint32_t*)(g_klo + base) = lo;
                } else {
                    split2(xa, xb, hi, lo);
                    *(uint32_t*)(g_vhi + base) = hi;
                    *(uint32_t*)(g_vlo + base) = lo;
                }
            }
        }
    }
}

// ---------------------------------------------------------------------------
// Kernel 2: rp = (q/8) @ (8*Wr)^T + br on tensor cores (bf16x3 split).
// CTA = 128 queries of one (b,h); 17 n-tiles of 16 over padded R=272.
// ---------------------------------------------------------------------------
#define RP_WRH  0
#define RP_WRL  (272 * SROW)           // 39,168
#define RP_SMEM (2 * 272 * SROW)       // 78,336

__global__ __launch_bounds__(256) void rp_mma_kernel(const float* __restrict__ br)
{
    extern __shared__ char smem[];
    const uint32_t sb = smem_u32(smem);
    const int tid = threadIdx.x, wid = tid >> 5, lane = tid & 31;
    const int g = lane >> 2, tq = lane & 3;
    const int q0 = blockIdx.x * 128;
    const int h  = blockIdx.y, b = blockIdx.z;
    const size_t hb64 = ((size_t)(b * H_ + h)) * S_ * HD_;

    // stage Q hi/lo, extract fragments
    {
        const __nv_bfloat16* qh = g_qhi + hb64 + (size_t)q0 * HD_;
        const __nv_bfloat16* ql = g_qlo + hb64 + (size_t)q0 * HD_;
#pragma unroll
        for (int t = 0; t < 4; t++) {
            int idx = tid + t * 256;
            int row = idx >> 3, c8 = idx & 7;
            *(uint4*)(smem + row * SROW + c8 * 16)         = *(const uint4*)(qh + row * HD_ + c8 * 8);
            *(uint4*)(smem + 18432 + row * SROW + c8 * 16) = *(const uint4*)(ql + row * HD_ + c8 * 8);
        }
    }
    __syncthreads();
    uint32_t qh[4][4], ql[4][4];
    {
        const uint32_t qa = sb + (uint32_t)((wid * 16 + ((lane >> 3) & 1) * 8 + (lane & 7)) * SROW
                                            + (lane >> 4) * 16);
#pragma unroll
        for (int ks = 0; ks < 4; ks++) {
            ldsm4(qh[ks], qa + ks * 32);
            ldsm4(ql[ks], qa + 18432 + ks * 32);
        }
    }
    __syncthreads();

    // load 8*Wr hi/lo into smem (272 rows x 64 bf16, K-major)
    for (int idx = tid; idx < 272 * HD_ / 8; idx += 256) {
        int row = idx >> 3, c8 = idx & 7;
        int dst = row * SROW + c8 * 16;
        *(uint4*)(smem + RP_WRH + dst) = *(const uint4*)(g_wr8h + row * HD_ + c8 * 8);
        *(uint4*)(smem + RP_WRL + dst) = *(const uint4*)(g_wr8l + row * HD_ + c8 * 8);
    }
    __syncthreads();

    const int i1 = q0 + wid * 16 + g;
    const int i2 = i1 + 8;
    float* rp1 = g_rp + ((size_t)(b * H_ + h) * S_ + i1) * RP;
    float* rp2 = rp1 + (size_t)8 * RP;

    const uint32_t b_ro = (uint32_t)((((lane >> 4) << 3) + (lane & 7)) * SROW
                                     + ((lane >> 3) & 1) * 16);

    for (int nc = 0; nc < 17; nc++) {
        float acc[2][4];
#pragma unroll
        for (int ntl = 0; ntl < 2; ntl++)
#pragma unroll
            for (int e = 0; e < 4; e++) acc[ntl][e] = 0.0f;

#pragma unroll
        for (int ks = 0; ks < 4; ks++) {
            uint32_t bH[4], bL[4];
            ldsm4(bH, sb + RP_WRH + nc * (16 * SROW) + b_ro + ks * 32);
            ldsm4(bL, sb + RP_WRL + nc * (16 * SROW) + b_ro + ks * 32);
#pragma unroll
            for (int ntl = 0; ntl < 2; ntl++) {
                mma16816(acc[ntl], qh[ks], bH + ntl * 2);
                mma16816(acc[ntl], qh[ks], bL + ntl * 2);
                mma16816(acc[ntl], ql[ks], bH + ntl * 2);
            }
        }

#pragma unroll
        for (int ntl = 0; ntl < 2; ntl++) {
            const int col = nc * 16 + ntl * 8 + tq * 2;
            float2 bv;
            if (col < 256)       bv = *(const float2*)(br + col);
            else if (col == 256) { bv.x = __ldg(br + 256); bv.y = 0.0f; }
            else                 { bv.x = 0.0f; bv.y = 0.0f; }
            float2 o1; o1.x = acc[ntl][0] + bv.x; o1.y = acc[ntl][1] + bv.y;
            float2 o2; o2.x = acc[ntl][2] + bv.x; o2.y = acc[ntl][3] + bv.y;
            *(float2*)(rp1 + col) = o1;
            *(float2*)(rp2 + col) = o2;
        }
    }
}

// ---------------------------------------------------------------------------
// Kernel 3: flash attention on tensor cores (bf16x3 split QK^T and PV),
// software exp, clip-hoisted rel-pos bias, cp.async 2-stage K/V pipeline.
// CTA = 128 queries of one (b,h); key tiles of 64.
// ---------------------------------------------------------------------------
#define AT_KH  0
#define AT_KL  9216
#define AT_VH  18432
#define AT_VL  27648
#define AST    36864                   // per-stage bytes
#define ATTN_SMEM (2 * AST)            // 73,728

__global__ __launch_bounds__(256) void attn_mma_kernel(float* __restrict__ out)
{
    extern __shared__ char smem[];
    const uint32_t sb = smem_u32(smem);
    const int tid = threadIdx.x, wid = tid >> 5, lane = tid & 31;
    const int g = lane >> 2, tq = lane & 3;
    const int q0 = blockIdx.x * 128;
    const int h  = blockIdx.y, b = blockIdx.z;
    const size_t hb64 = ((size_t)(b * H_ + h)) * S_ * HD_;

    // ---- stage Q (hi at 0, lo at 18432), build register fragments ----
    {
        const __nv_bfloat16* qhp = g_qhi + hb64 + (size_t)q0 * HD_;
        const __nv_bfloat16* qlp = g_qlo + hb64 + (size_t)q0 * HD_;
#pragma unroll
        for (int t = 0; t < 4; t++) {
            int idx = tid + t * 256;
            int row = idx >> 3, c8 = idx & 7;
            *(uint4*)(smem + row * SROW + c8 * 16)         = *(const uint4*)(qhp + row * HD_ + c8 * 8);
            *(uint4*)(smem + 18432 + row * SROW + c8 * 16) = *(const uint4*)(qlp + row * HD_ + c8 * 8);
        }
    }
    __syncthreads();
    uint32_t qh[4][4], ql[4][4];
    {
        const uint32_t qa = sb + (uint32_t)((wid * 16 + ((lane >> 3) & 1) * 8 + (lane & 7)) * SROW
                                            + (lane >> 4) * 16);
#pragma unroll
        for (int ks = 0; ks < 4; ks++) {
            ldsm4(qh[ks], qa + ks * 32);
            ldsm4(ql[ks], qa + 18432 + ks * 32);
        }
    }
    __syncthreads();

    float oacc[8][4];
#pragma unroll
    for (int nt = 0; nt < 8; nt++)
#pragma unroll
        for (int e = 0; e < 4; e++) oacc[nt][e] = 0.0f;
    float mrow[2] = {-1e30f, -1e30f}, lrow[2] = {0.0f, 0.0f};

    const int i1 = q0 + wid * 16 + g;
    const int i2 = i1 + 8;
    const float* rp1 = g_rp + ((size_t)(b * H_ + h) * S_ + i1) * RP;
    const float* rp2 = rp1 + (size_t)8 * RP;
    const float rp1_lo = __ldg(rp1), rp1_hi = __ldg(rp1 + 2 * WIN_);
    const float rp2_lo = __ldg(rp2), rp2_hi = __ldg(rp2 + 2 * WIN_);

    const __nv_bfloat16* kh = g_khi + hb64;
    const __nv_bfloat16* kl = g_klo + hb64;
    const __nv_bfloat16* vh = g_vhi + hb64;
    const __nv_bfloat16* vl = g_vlo + hb64;

    const uint32_t koff = (uint32_t)((((lane >> 4) << 3) + (lane & 7)) * SROW + ((lane >> 3) & 1) * 16);
    const uint32_t voff = (uint32_t)((((lane >> 3) & 1) * 8 + (lane & 7)) * SROW + (lane >> 4) * 16);

    auto issue_kv = [&](int kt, int s) {
        const uint32_t sbs = sb + s * AST;
#pragma unroll
        for (int t = 0; t < 2; t++) {
            int idx = tid + t * 256;
            int row = idx >> 3, c8 = idx & 7;
            size_t src = (size_t)(kt * 64 + row) * HD_ + c8 * 8;
            uint32_t dst = (uint32_t)(row * SROW + c8 * 16);
            cpasync16(sbs + AT_KH + dst, kh + src);
            cpasync16(sbs + AT_KL + dst, kl + src);
            cpasync16(sbs + AT_VH + dst, vh + src);
            cpasync16(sbs + AT_VL + dst, vl + src);
        }
    };

    issue_kv(0, 0);
    CP_COMMIT();

    for (int kt = 0; kt < S_ / 64; kt++) {
        const int kt64 = kt * 64;
        const int s = kt & 1;
        const uint32_t sbs = sb + s * AST;
        if (kt + 1 < S_ / 64) issue_kv(kt + 1, s ^ 1);
        CP_COMMIT();
        CP_WAIT1();
        __syncthreads();

        // ---- scores S = Q.K^T (3-way split) ----
        float sacc[8][4];
#pragma unroll
        for (int nt = 0; nt < 8; nt++)
#pragma unroll
            for (int e = 0; e < 4; e++) sacc[nt][e] = 0.0f;
#pragma unroll
        for (int ks = 0; ks < 4; ks++) {
#pragma unroll
            for (int ntp = 0; ntp < 4; ntp++) {
                uint32_t bH[4], bL[4];
                ldsm4(bH, sbs + AT_KH + ntp * (16 * SROW) + ks * 32 + koff);
                ldsm4(bL, sbs + AT_KL + ntp * (16 * SROW) + ks * 32 + koff);
#pragma unroll
                for (int ntl = 0; ntl < 2; ntl++) {
                    float* d = sacc[ntp * 2 + ntl];
                    mma16816(d, qh[ks], bH + ntl * 2);
                    mma16816(d, qh[ks], bL + ntl * 2);
                    mma16816(d, ql[ks], bH + ntl * 2);
                }
            }
        }

        // ---- rel-pos bias: hoisted constants for fully-clipped tiles ----
        if (i1 >= kt64 + 191) {
#pragma unroll
            for (int nt = 0; nt < 8; nt++) { sacc[nt][0] += rp1_lo; sacc[nt][1] += rp1_lo; }
        } else if (i1 + WIN_ <= kt64) {
#pragma unroll
            for (int nt = 0; nt < 8; nt++) { sacc[nt][0] += rp1_hi; sacc[nt][1] += rp1_hi; }
        } else {
#pragma unroll
            for (int nt = 0; nt < 8; nt++)
#pragma unroll
                for (int e = 0; e < 2; e++) {
                    int off = kt64 + nt * 8 + tq * 2 + e - i1;
                    off = off < -WIN_ ? -WIN_ : (off > WIN_ ? WIN_ : off);
                    sacc[nt][e] += __ldg(rp1 + off + WIN_);
                }
        }
        if (i2 >= kt64 + 191) {
#pragma unroll
            for (int nt = 0; nt < 8; nt++) { sacc[nt][2] += rp2_lo; sacc[nt][3] += rp2_lo; }
        } else if (i2 + WIN_ <= kt64) {
#pragma unroll
            for (int nt = 0; nt < 8; nt++) { sacc[nt][2] += rp2_hi; sacc[nt][3] += rp2_hi; }
        } else {
#pragma unroll
            for (int nt = 0; nt < 8; nt++)
#pragma unroll
                for (int e = 0; e < 2; e++) {
                    int off = kt64 + nt * 8 + tq * 2 + e - i2;
                    off = off < -WIN_ ? -WIN_ : (off > WIN_ ? WIN_ : off);
                    sacc[nt][2 + e] += __ldg(rp2 + off + WIN_);
                }
        }

        // ---- online softmax ----
        float mx1 = -1e30f, mx2 = -1e30f;
#pragma unroll
        for (int nt = 0; nt < 8; nt++) {
            mx1 = fmaxf(mx1, fmaxf(sacc[nt][0], sacc[nt][1]));
            mx2 = fmaxf(mx2, fmaxf(sacc[nt][2], sacc[nt][3]));
        }
        mx1 = fmaxf(mx1, __shfl_xor_sync(0xffffffffu, mx1, 1));
        mx1 = fmaxf(mx1, __shfl_xor_sync(0xffffffffu, mx1, 2));
        mx2 = fmaxf(mx2, __shfl_xor_sync(0xffffffffu, mx2, 1));
        mx2 = fmaxf(mx2, __shfl_xor_sync(0xffffffffu, mx2, 2));
        float mn1 = fmaxf(mrow[0], mx1), mn2 = fmaxf(mrow[1], mx2);
        float al1 = fexp(mrow[0] - mn1), al2 = fexp(mrow[1] - mn2);
        mrow[0] = mn1; mrow[1] = mn2;
        float sum1 = 0.0f, sum2 = 0.0f;
#pragma unroll
        for (int nt = 0; nt < 8; nt++) {
            float p0 = fexp(sacc[nt][0] - mn1), p1 = fexp(sacc[nt][1] - mn1);
            float p2 = fexp(sacc[nt][2] - mn2), p3 = fexp(sacc[nt][3] - mn2);
            sacc[nt][0] = p0; sacc[nt][1] = p1; sacc[nt][2] = p2; sacc[nt][3] = p3;
            sum1 += p0 + p1; sum2 += p2 + p3;
        }
        sum1 += __shfl_xor_sync(0xffffffffu, sum1, 1);
        sum1 += __shfl_xor_sync(0xffffffffu, sum1, 2);
        sum2 += __shfl_xor_sync(0xffffffffu, sum2, 1);
        sum2 += __shfl_xor_sync(0xffffffffu, sum2, 2);
        lrow[0] = lrow[0] * al1 + sum1;
        lrow[1] = lrow[1] * al2 + sum2;
#pragma unroll
        for (int nt = 0; nt < 8; nt++) {
            oacc[nt][0] *= al1; oacc[nt][1] *= al1;
            oacc[nt][2] *= al2; oacc[nt][3] *= al2;
        }

        // ---- O += P.V per 16-key chunk (low live regs) ----
#pragma unroll
        for (int kc = 0; kc < 4; kc++) {
            uint32_t ph[4], pl[4];
            split2(sacc[2*kc][0],   sacc[2*kc][1],   ph[0], pl[0]);
            split2(sacc[2*kc][2],   sacc[2*kc][3],   ph[1], pl[1]);
            split2(sacc[2*kc+1][0], sacc[2*kc+1][1], ph[2], pl[2]);
            split2(sacc[2*kc+1][2], sacc[2*kc+1][3], ph[3], pl[3]);
#pragma unroll
            for (int ndp = 0; ndp < 4; ndp++) {
                uint32_t vH[4], vL[4];
                ldsm4t(vH, sbs + AT_VH + kc * (16 * SROW) + ndp * 32 + voff);
                ldsm4t(vL, sbs + AT_VL + kc * (16 * SROW) + ndp * 32 + voff);
#pragma unroll
                for (int ntl = 0; ntl < 2; ntl++) {
                    float* d = oacc[ndp * 2 + ntl];
                    mma16816(d, ph, vH + ntl * 2);
                    mma16816(d, ph, vL + ntl * 2);
                    mma16816(d, pl, vH + ntl * 2);
                }
            }
        }
        __syncthreads();
    }

    // ---- epilogue ----
    const float inv1 = 1.0f / lrow[0], inv2 = 1.0f / lrow[1];
#pragma unroll
    for (int nt = 0; nt < 8; nt++) {
        const int col = h * HD_ + nt * 8 + tq * 2;
        float2 o1; o1.x = oacc[nt][0] * inv1; o1.y = oacc[nt][1] * inv1;
        float2 o2; o2.x = oacc[nt][2] * inv2; o2.y = oacc[nt][3] * inv2;
        *(float2*)(out + (size_t)(b * S_ + i1) * D_ + col) = o1;
        *(float2*)(out + (size_t)(b * S_ + i2) * D_ + col) = o2;
    }
}

// ---------------------------------------------------------------------------
extern "C" void kernel_launch(void* const* d_in, const int* in_sizes, int n_in,
                              void* d_out, int out_size)
{
    const float* x    = (const float*)d_in[0];
    const float* Wqkv = (const float*)d_in[1];
    const float* bqkv = (const float*)d_in[2];
    const float* Wr   = (const float*)d_in[3];
    const float* br   = (const float*)d_in[4];
    float* out = (float*)d_out;

    __nv_bfloat162 *xhi, *xlo, *whi, *wlo;
    cudaGetSymbolAddress((void**)&xhi, g_xhi);
    cudaGetSymbolAddress((void**)&xlo, g_xlo);
    cudaGetSymbolAddress((void**)&whi, g_whi);
    cudaGetSymbolAddress((void**)&wlo, g_wlo);

    split_bf16_kernel<<<(TOK * D_ / 4 + 255) / 256, 256>>>(
        (const float4*)x, xhi, xlo, TOK * D_ / 4);
    split_bf16_kernel<<<(C3 * D_ / 4 + 255) / 256, 256>>>(
        (const float4*)Wqkv, whi, wlo, C3 * D_ / 4);
    split_wr8_kernel<<<(272 * HD_ / 2 + 255) / 256, 256>>>(Wr);

    cudaFuncSetAttribute(qkv_mma_kernel,
                         cudaFuncAttributeMaxDynamicSharedMemorySize, QKV_SMEM);
    dim3 g1(C3 / 128, TOK / 128);   // (24, 32)
    qkv_mma_kernel<<<g1, 256, QKV_SMEM>>>(bqkv);

    cudaFuncSetAttribute(rp_mma_kernel,
                         cudaFuncAttributeMaxDynamicSharedMemorySize, RP_SMEM);
    dim3 g2(S_ / 128, H_, B_);      // (16, 16, 2)
    rp_mma_kernel<<<g2, 256, RP_SMEM>>>(br);

    cudaFuncSetAttribute(attn_mma_kernel,
                         cudaFuncAttributeMaxDynamicSharedMemorySize, ATTN_SMEM);
    dim3 g3(S_ / 128, H_, B_);      // (16, 16, 2)
    attn_mma_kernel<<<g3, 256, ATTN_SMEM>>>(out);
}